// round 9
// baseline (speedup 1.0000x reference)
#include <cuda_runtime.h>
#include <cuda_bf16.h>
#include <cuda_fp16.h>
#include <cstdint>

#define N_NODES 10000
#define N_EDGES 64000
#define N_GRAPHS 64
#define HID 64
#define ET 128                    // edges per GEMM subtile
#define NTILES (N_EDGES / ET)     // 500 subtiles; 250 CTAs x 2
#define NSLICE 65                 // 64 w2 slices + 1 bias slice
#define FRAG_PER_SLICE 512        // 4 kt x 4 np x 32 lanes, uint4 each = 8KB

// node_enc dynamic smem: ws(8192f) + bs(64f) + xs(128*129f)
#define ENC_SMEM ((8192 + 64 + 128 * 129) * 4)

// ---------------- scratch (device globals; no allocation allowed) ----------------
__device__ float    g_h0[N_NODES * HID];
__device__ float    g_h1[N_NODES * HID];
__device__ float    g_agg[N_NODES * HID];
__device__ __half   g_tt1[NTILES * HID * ET];     // edge-MLP layer1 (fp16): [subtile][k][e]
__device__ __half   g_tt2[NTILES * HID * ET];     // edge-MLP layer2 (fp16): [subtile][k][e]
__device__ uint32_t g_hsth[N_EDGES * 32];         // gathered h[src] as half2: [e][i/2]
__device__ uint4    g_bfrag[2 * NSLICE * FRAG_PER_SLICE]; // w2 (+bias) mma-fragment order
__device__ int      g_src[N_EDGES];
__device__ int      g_dst[N_EDGES];
__device__ int      g_bat[N_NODES];
__device__ float    g_hg[N_GRAPHS * HID];

// ---------------- aux stream/events (created at static-init; reused every call) ----------------
struct Aux {
    cudaStream_t s1;
    cudaEvent_t fork, join;
    Aux() {
        cudaStreamCreateWithFlags(&s1, cudaStreamNonBlocking);
        cudaEventCreateWithFlags(&fork, cudaEventDisableTiming);
        cudaEventCreateWithFlags(&join, cudaEventDisableTiming);
    }
};
static Aux g_aux;

__device__ __forceinline__ float lrelu(float v) { return v > 0.f ? v : 0.01f * v; }

// ---------------- PTX helpers ----------------
__device__ __forceinline__ void cp16(void* s, const void* g) {
    unsigned sa = (unsigned)__cvta_generic_to_shared(s);
    asm volatile("cp.async.cg.shared.global [%0], [%1], 16;" :: "r"(sa), "l"(g));
}
__device__ __forceinline__ void cp_commit() { asm volatile("cp.async.commit_group;"); }

// fp16 mma: D[16x8] += A[16x16] * B[16x8]
__device__ __forceinline__ void mma16(float* c, const uint32_t* a, uint32_t b0, uint32_t b1) {
    asm volatile(
        "mma.sync.aligned.m16n8k16.row.col.f32.f16.f16.f32 "
        "{%0,%1,%2,%3}, {%4,%5,%6,%7}, {%8,%9}, {%0,%1,%2,%3};"
        : "+f"(c[0]), "+f"(c[1]), "+f"(c[2]), "+f"(c[3])
        : "r"(a[0]), "r"(a[1]), "r"(a[2]), "r"(a[3]), "r"(b0), "r"(b1));
}

// vectorized global reduction (sm_90+)
__device__ __forceinline__ void red2(float* p, float x, float y) {
    asm volatile("red.global.add.v2.f32 [%0], {%1, %2};" :: "l"(p), "f"(x), "f"(y) : "memory");
}

// ---------------- index conversion (int64-vs-int32 auto-detect) + hg zero ----------------
__global__ void convert_idx_kernel(const void* ei, const void* bat) {
    __shared__ int s64;
    if (threadIdx.x == 0) {
        const unsigned* w = (const unsigned*)ei;
        int z = 0;
        for (int i = 1; i < 256; i += 2) z += (w[i] == 0u);
        s64 = (z > 64);
    }
    __syncthreads();
    const bool is64 = (s64 != 0);
    int stride = blockDim.x * gridDim.x;
    int gid = blockIdx.x * blockDim.x + threadIdx.x;
    for (int g = gid; g < N_EDGES; g += stride) {
        if (is64) {
            g_src[g] = (int)((const long long*)ei)[g];
            g_dst[g] = (int)((const long long*)ei)[N_EDGES + g];
        } else {
            g_src[g] = ((const int*)ei)[g];
            g_dst[g] = ((const int*)ei)[N_EDGES + g];
        }
    }
    for (int g = gid; g < N_NODES; g += stride) {
        g_bat[g] = is64 ? (int)((const long long*)bat)[g] : ((const int*)bat)[g];
    }
    if (gid < N_GRAPHS * HID) g_hg[gid] = 0.f;
}

// ---------------- node encoder: thread-per-node, broadcast float4 weights ----------------
__global__ void __launch_bounds__(128) node_enc_kernel(
    const float* __restrict__ x, const float* __restrict__ w,
    const float* __restrict__ b, float* __restrict__ h) {
    extern __shared__ float sm[];
    float* ws = sm;            // [128][64]
    float* bs = sm + 8192;     // [64]
    float* xs = sm + 8256;     // [128][129] padded
    const int tid = threadIdx.x;
    const int n0 = blockIdx.x * 128;

    for (int idx = tid; idx < 8192; idx += 128) ws[idx] = w[idx];
    if (tid < 64) bs[tid] = b[tid];
    for (int q = 0; q < 128; ++q) {
        int r = q, c = tid;  // coalesced global read, padded smem store
        int n = n0 + r;
        xs[r * 129 + c] = (n < N_NODES) ? x[(size_t)n * 128 + c] : 0.f;
    }
    __syncthreads();

    const int n = n0 + tid;
    if (n >= N_NODES) return;

    float4 acc[16];
#pragma unroll
    for (int og = 0; og < 16; ++og) acc[og] = *(const float4*)&bs[4 * og];

#pragma unroll
    for (int ig = 0; ig < 4; ++ig) {
        float xr[32];
#pragma unroll
        for (int j = 0; j < 32; ++j) xr[j] = xs[tid * 129 + ig * 32 + j];  // bank (tid+j)&31
#pragma unroll
        for (int j = 0; j < 32; ++j) {
            float v = xr[j];
            const float* wr = ws + (ig * 32 + j) * 64;
#pragma unroll
            for (int og = 0; og < 16; ++og) {
                float4 wv = *(const float4*)&wr[4 * og];  // broadcast LDS.128
                acc[og].x += v * wv.x; acc[og].y += v * wv.y;
                acc[og].z += v * wv.z; acc[og].w += v * wv.w;
            }
        }
    }

    float* hp = h + (size_t)n * 64;
#pragma unroll
    for (int og = 0; og < 16; ++og) {
        float4 o;
        o.x = lrelu(acc[og].x); o.y = lrelu(acc[og].y);
        o.z = lrelu(acc[og].z); o.w = lrelu(acc[og].w);
        *(float4*)&hp[4 * og] = o;
    }
}

// ---------------- fused edge MLP (both layers): one thread per edge, broadcast weights ----------------
__global__ void __launch_bounds__(128) edge_mlp2_kernel(
    const float* __restrict__ ea,
    const float* __restrict__ w1a, const float* __restrict__ b1a,
    const float* __restrict__ w1b, const float* __restrict__ b1b,
    __half* __restrict__ tt1, __half* __restrict__ tt2) {
    __shared__ float eas[128 * 33];
    __shared__ float wA[32 * 64];
    __shared__ float wB[32 * 64];
    __shared__ float bA[64], bB[64];
    const int tid = threadIdx.x;
    const int tile = blockIdx.x;
    for (int idx = tid; idx < 128 * 32; idx += 128) {
        int e = idx >> 5, j = idx & 31;
        eas[e * 33 + j] = ea[tile * 4096 + idx];
    }
    for (int idx = tid; idx < 2048; idx += 128) { wA[idx] = w1a[idx]; wB[idx] = w1b[idx]; }
    if (tid < 64) { bA[tid] = b1a[tid]; bB[tid] = b1b[tid]; }
    __syncthreads();

    float ear[32];
#pragma unroll
    for (int j = 0; j < 32; ++j) ear[j] = eas[tid * 33 + j];

    __half* t1 = tt1 + tile * 8192 + tid;
    __half* t2 = tt2 + tile * 8192 + tid;
#pragma unroll 2
    for (int og = 0; og < 16; ++og) {
        float4 a1 = *(const float4*)&bA[4 * og];
        float4 a2 = *(const float4*)&bB[4 * og];
#pragma unroll
        for (int j = 0; j < 32; ++j) {
            float v = ear[j];
            float4 wa = *(const float4*)&wA[j * 64 + 4 * og];
            float4 wb = *(const float4*)&wB[j * 64 + 4 * og];
            a1.x += v * wa.x; a1.y += v * wa.y; a1.z += v * wa.z; a1.w += v * wa.w;
            a2.x += v * wb.x; a2.y += v * wb.y; a2.z += v * wb.z; a2.w += v * wb.w;
        }
        t1[(4 * og + 0) * 128] = __float2half(fmaxf(a1.x, 0.f));
        t1[(4 * og + 1) * 128] = __float2half(fmaxf(a1.y, 0.f));
        t1[(4 * og + 2) * 128] = __float2half(fmaxf(a1.z, 0.f));
        t1[(4 * og + 3) * 128] = __float2half(fmaxf(a1.w, 0.f));
        t2[(4 * og + 0) * 128] = __float2half(fmaxf(a2.x, 0.f));
        t2[(4 * og + 1) * 128] = __float2half(fmaxf(a2.y, 0.f));
        t2[(4 * og + 2) * 128] = __float2half(fmaxf(a2.z, 0.f));
        t2[(4 * og + 3) * 128] = __float2half(fmaxf(a2.w, 0.f));
    }
}

// ---------------- gather h[src] -> half2 [e][i/2]; also zeroes agg ----------------
__global__ void gather_kernel(const float* __restrict__ h, uint32_t* __restrict__ hsth,
                              float* __restrict__ agg) {
    int id = blockIdx.x * blockDim.x + threadIdx.x;  // < N_EDGES*32
    int p = id & 31;
    int e = id >> 5;
    float2 v = *(const float2*)(h + (size_t)g_src[e] * HID + 2 * p);
    __half2 hv = __floats2half2_rn(v.x, v.y);
    hsth[id] = *reinterpret_cast<uint32_t*>(&hv);
    if (id < N_NODES * HID) agg[id] = 0.f;
}

// ---------------- B prep (both layers): w2 (+b2) -> mma fragment order ----------------
__global__ void bprep2_kernel(const float* __restrict__ w2a, const float* __restrict__ b2a,
                              const float* __restrict__ w2b, const float* __restrict__ b2b,
                              uint4* __restrict__ bf) {
    int id = blockIdx.x * blockDim.x + threadIdx.x;  // < 2*65*512
    if (id >= 2 * NSLICE * FRAG_PER_SLICE) return;
    int layer = id >= NSLICE * FRAG_PER_SLICE;
    int rid = id - layer * NSLICE * FRAG_PER_SLICE;
    int s = rid >> 9;
    int f = rid & 511;
    int kt = f >> 7, np = (f >> 5) & 3, lane = f & 31;
    int tig = lane & 3, g = lane >> 2;
    const float* w2 = layer ? w2b : w2a;
    const float* b2 = layer ? b2b : b2a;
    int o0 = g + 16 * np, o1 = o0 + 8;
    int p0 = kt * 8 + tig, p1 = p0 + 4;
    auto rd = [&](int i, int o) -> float {
        return (s < 64) ? w2[(s << 12) + (i << 6) + o] : b2[(i << 6) + o];
    };
    auto pk = [&](int p, int o) -> uint32_t {
        __half2 hv = __floats2half2_rn(rd(2 * p, o), rd(2 * p + 1, o));
        return *reinterpret_cast<uint32_t*>(&hv);
    };
    uint4 v;
    v.x = pk(p0, o0); v.y = pk(p1, o0); v.z = pk(p0, o1); v.w = pk(p1, o1);
    bf[id] = v;
}

// ---------------- fp16 mma.sync message GEMM + scatter (256 edges / CTA, 8 warps) ----------------
__global__ void __launch_bounds__(256, 2) msg_mma_kernel(
    const __half* __restrict__ tt, const uint32_t* __restrict__ hsth,
    const uint4* __restrict__ bf, float* __restrict__ agg) {
    __shared__ uint4 Bs[2][FRAG_PER_SLICE];
    const int tid = threadIdx.x;
    const int w = tid >> 5, lane = tid & 31;
    const int g = lane >> 2, tig = lane & 3;
    const int subtile = 2 * blockIdx.x + (w >> 2);
    const int wl = w & 3;

    {
        cp16(&Bs[0][tid], bf + tid);
        cp16(&Bs[0][tid + 256], bf + tid + 256);
        cp_commit();
    }

    uint32_t hh[2][2][8];
    {
        const uint32_t* hb = hsth + ((size_t)subtile * 128 + wl * 32 + g) * 32 + tig;
#pragma unroll
        for (int m = 0; m < 2; ++m)
#pragma unroll
            for (int r = 0; r < 2; ++r) {
                const uint32_t* hp = hb + (m * 16 + r * 8) * 32;
#pragma unroll
                for (int j = 0; j < 8; ++j) hh[m][r][j] = hp[4 * j];
            }
    }

    float C[2][8][4];
#pragma unroll
    for (int m = 0; m < 2; ++m)
#pragma unroll
        for (int nt = 0; nt < 8; ++nt)
#pragma unroll
            for (int q = 0; q < 4; ++q) C[m][nt][q] = 0.f;

    const __half* tbase = tt + (size_t)subtile * 8192 + wl * 32 + g;

    for (int k = 0; k < NSLICE; ++k) {
        const int b = k & 1;
        asm volatile("cp.async.wait_group 0;");
        __syncthreads();
        if (k < NSLICE - 1) {
            const uint4* s = bf + (size_t)(k + 1) * FRAG_PER_SLICE;
            uint4* d = Bs[b ^ 1];
            cp16(&d[tid], s + tid);
            cp16(&d[tid + 256], s + tid + 256);
            cp_commit();
        }

        __half2 t2[4];
        if (k < 64) {
            const __half* tp = tbase + k * 128;
            t2[0] = __half2half2(tp[0]);
            t2[1] = __half2half2(tp[8]);
            t2[2] = __half2half2(tp[16]);
            t2[3] = __half2half2(tp[24]);
        } else {
            t2[0] = t2[1] = t2[2] = t2[3] = __float2half2_rn(1.f);
        }

        const uint4* B = Bs[b];
#pragma unroll
        for (int kt = 0; kt < 4; ++kt) {
            __half2 a[2][4];
#pragma unroll
            for (int m = 0; m < 2; ++m) {
                a[m][0] = __hmul2(*(const __half2*)&hh[m][0][2 * kt + 0], t2[2 * m + 0]);
                a[m][1] = __hmul2(*(const __half2*)&hh[m][1][2 * kt + 0], t2[2 * m + 1]);
                a[m][2] = __hmul2(*(const __half2*)&hh[m][0][2 * kt + 1], t2[2 * m + 0]);
                a[m][3] = __hmul2(*(const __half2*)&hh[m][1][2 * kt + 1], t2[2 * m + 1]);
            }
#pragma unroll
            for (int np = 0; np < 4; ++np) {
                uint4 bv = B[(kt * 4 + np) * 32 + lane];
                mma16(C[0][2 * np + 0], reinterpret_cast<const uint32_t*>(a[0]), bv.x, bv.y);
                mma16(C[1][2 * np + 0], reinterpret_cast<const uint32_t*>(a[1]), bv.x, bv.y);
                mma16(C[0][2 * np + 1], reinterpret_cast<const uint32_t*>(a[0]), bv.z, bv.w);
                mma16(C[1][2 * np + 1], reinterpret_cast<const uint32_t*>(a[1]), bv.z, bv.w);
            }
        }
    }

    const int ebase = subtile * 128 + wl * 32 + g;
#pragma unroll
    for (int m = 0; m < 2; ++m) {
        int d0 = g_dst[ebase + m * 16];
        int d1 = g_dst[ebase + m * 16 + 8];
        float* p0 = agg + (size_t)d0 * 64 + 2 * tig;
        float* p1 = agg + (size_t)d1 * 64 + 2 * tig;
#pragma unroll
        for (int nt = 0; nt < 8; ++nt) {
            red2(p0 + nt * 8, C[m][nt][0], C[m][nt][1]);
            red2(p1 + nt * 8, C[m][nt][2], C[m][nt][3]);
        }
    }
}

// ---------------- node update: thread-per-node, broadcast float4 root ----------------
__global__ void __launch_bounds__(128) node_update_kernel(
    const float* __restrict__ hin, const float* __restrict__ agg,
    const float* __restrict__ root, const float* __restrict__ bias,
    float* __restrict__ hout) {
    __shared__ float rs[64 * 64];
    __shared__ float bs[64];
    const int tid = threadIdx.x;
    for (int idx = tid; idx < 4096; idx += 128) rs[idx] = root[idx];
    if (tid < 64) bs[tid] = bias[tid];
    __syncthreads();

    const int n = blockIdx.x * 128 + tid;
    if (n >= N_NODES) return;

    const float* ap = agg + (size_t)n * 64;
    float4 acc[16];
#pragma unroll
    for (int og = 0; og < 16; ++og) {
        float4 a = *(const float4*)&ap[4 * og];
        const float4 bv = *(const float4*)&bs[4 * og];
        a.x += bv.x; a.y += bv.y; a.z += bv.z; a.w += bv.w;
        acc[og] = a;
    }

    const float* hp = hin + (size_t)n * 64;
#pragma unroll
    for (int ig = 0; ig < 4; ++ig) {
        float4 hv[4];
#pragma unroll
        for (int q = 0; q < 4; ++q) hv[q] = *(const float4*)&hp[ig * 16 + 4 * q];
        const float* hr = (const float*)hv;
#pragma unroll
        for (int j = 0; j < 16; ++j) {
            float v = hr[j];
            const float* rr = rs + (ig * 16 + j) * 64;
#pragma unroll
            for (int og = 0; og < 16; ++og) {
                float4 rv = *(const float4*)&rr[4 * og];  // broadcast LDS.128
                acc[og].x += v * rv.x; acc[og].y += v * rv.y;
                acc[og].z += v * rv.z; acc[og].w += v * rv.w;
            }
        }
    }

    float* op = hout + (size_t)n * 64;
#pragma unroll
    for (int og = 0; og < 16; ++og) {
        float4 o;
        o.x = lrelu(acc[og].x); o.y = lrelu(acc[og].y);
        o.z = lrelu(acc[og].z); o.w = lrelu(acc[og].w);
        *(float4*)&op[4 * og] = o;
    }
}

// ---------------- global add pool (batch-sorted running-sum flush) ----------------
__global__ void pool_kernel(const float* __restrict__ h) {
    const int tid = threadIdx.x;
    const int o = tid & 63, q = tid >> 6;
    const int nbase = blockIdx.x * 256 + q * 64;
    float run = 0.f;
    int curb = -1;
    for (int j = 0; j < 64; ++j) {
        int n = nbase + j;
        if (n >= N_NODES) break;
        int bn = g_bat[n];
        if (bn != curb) {
            if (curb >= 0) atomicAdd(&g_hg[curb * 64 + o], run);
            run = 0.f;
            curb = bn;
        }
        run += h[(size_t)n * 64 + o];
    }
    if (curb >= 0) atomicAdd(&g_hg[curb * 64 + o], run);
}

// ---------------- readout head ----------------
__global__ void head_kernel(const float* __restrict__ fc1w, const float* __restrict__ fc1b,
                            const float* __restrict__ fc2w, const float* __restrict__ fc2b,
                            float* __restrict__ out) {
    __shared__ float hs[N_GRAPHS * HID];
    int g = threadIdx.x;
    for (int i = g; i < N_GRAPHS * HID; i += 64) hs[i] = g_hg[i];
    __syncthreads();
    float acc = fc2b[0];
#pragma unroll 4
    for (int j = 0; j < 32; ++j) {
        float s = fc1b[j];
#pragma unroll 8
        for (int i = 0; i < 64; ++i) s += hs[g * 64 + i] * fc1w[i * 32 + j];
        acc += lrelu(s) * fc2w[j];
    }
    out[g] = acc;
}

// ---------------- launch ----------------
extern "C" void kernel_launch(void* const* d_in, const int* in_sizes, int n_in,
                              void* d_out, int out_size) {
    const float* x     = (const float*)d_in[0];
    const void*  ei    = d_in[1];
    const float* ea    = (const float*)d_in[2];
    const void*  bat   = d_in[3];
    const float* nfc_w = (const float*)d_in[4];
    const float* nfc_b = (const float*)d_in[5];
    const float* e1w1  = (const float*)d_in[6];
    const float* e1b1  = (const float*)d_in[7];
    const float* e1w2  = (const float*)d_in[8];
    const float* e1b2  = (const float*)d_in[9];
    const float* root1 = (const float*)d_in[10];
    const float* bias1 = (const float*)d_in[11];
    const float* e2w1  = (const float*)d_in[12];
    const float* e2b1  = (const float*)d_in[13];
    const float* e2w2  = (const float*)d_in[14];
    const float* e2b2  = (const float*)d_in[15];
    const float* root2 = (const float*)d_in[16];
    const float* bias2 = (const float*)d_in[17];
    const float* fc1w  = (const float*)d_in[18];
    const float* fc1b  = (const float*)d_in[19];
    const float* fc2w  = (const float*)d_in[20];
    const float* fc2b  = (const float*)d_in[21];
    float* out = (float*)d_out;

    float *h0, *h1, *agg, *hg;
    __half *tt1, *tt2;
    uint32_t* hsth;
    uint4* bfp;
    cudaGetSymbolAddress((void**)&h0, g_h0);
    cudaGetSymbolAddress((void**)&h1, g_h1);
    cudaGetSymbolAddress((void**)&agg, g_agg);
    cudaGetSymbolAddress((void**)&tt1, g_tt1);
    cudaGetSymbolAddress((void**)&tt2, g_tt2);
    cudaGetSymbolAddress((void**)&hg, g_hg);
    cudaGetSymbolAddress((void**)&hsth, g_hsth);
    cudaGetSymbolAddress((void**)&bfp, g_bfrag);

    cudaFuncSetAttribute(node_enc_kernel, cudaFuncAttributeMaxDynamicSharedMemorySize, ENC_SMEM);

    // fork: edge MLP + weight prep on aux stream, node path on main stream
    cudaEventRecord(g_aux.fork, 0);
    cudaStreamWaitEvent(g_aux.s1, g_aux.fork, 0);
    edge_mlp2_kernel<<<NTILES, 128, 0, g_aux.s1>>>(ea, e1w1, e1b1, e2w1, e2b1, tt1, tt2);
    bprep2_kernel<<<(2 * NSLICE * FRAG_PER_SLICE + 255) / 256, 256, 0, g_aux.s1>>>(
        e1w2, e1b2, e2w2, e2b2, bfp);
    cudaEventRecord(g_aux.join, g_aux.s1);

    convert_idx_kernel<<<256, 256>>>(ei, bat);
    node_enc_kernel<<<(N_NODES + 127) / 128, 128, ENC_SMEM>>>(x, nfc_w, nfc_b, h0);
    gather_kernel<<<N_EDGES * 32 / 256, 256>>>(h0, hsth, agg);

    cudaStreamWaitEvent(0, g_aux.join, 0);

    // layer 1
    msg_mma_kernel<<<NTILES / 2, 256>>>(tt1, hsth, bfp, agg);
    node_update_kernel<<<(N_NODES + 127) / 128, 128>>>(h0, agg, root1, bias1, h1);

    // layer 2
    gather_kernel<<<N_EDGES * 32 / 256, 256>>>(h1, hsth, agg);
    msg_mma_kernel<<<NTILES / 2, 256>>>(tt2, hsth, bfp + (size_t)NSLICE * FRAG_PER_SLICE, agg);
    node_update_kernel<<<(N_NODES + 127) / 128, 128>>>(h1, agg, root2, bias2, h0);

    // pool + head
    pool_kernel<<<(N_NODES + 255) / 256, 256>>>(h0);
    head_kernel<<<1, 64>>>(fc1w, fc1b, fc2w, fc2b, out);
}

// round 12
// speedup vs baseline: 1.0247x; 1.0247x over previous
#include <cuda_runtime.h>
#include <cuda_bf16.h>
#include <cuda_fp16.h>
#include <cstdint>

#define N_NODES 10000
#define N_EDGES 64000
#define N_GRAPHS 64
#define HID 64
#define ET 128                    // edges per GEMM subtile
#define NTILES (N_EDGES / ET)     // 500 subtiles; 250 CTAs x 2
#define NSLICE 65                 // 64 w2 slices + 1 bias slice
#define FRAG_PER_SLICE 512        // 4 kt x 4 np x 32 lanes, uint4 each = 8KB

// ---------------- scratch (device globals; no allocation allowed) ----------------
__device__ float    g_h0[N_NODES * HID];
__device__ float    g_h1[N_NODES * HID];
__device__ float    g_agg[N_NODES * HID];
__device__ __half   g_tt1[NTILES * HID * ET];     // edge-MLP layer1 (fp16): [subtile][k][e]
__device__ __half   g_tt2[NTILES * HID * ET];     // edge-MLP layer2 (fp16): [subtile][k][e]
__device__ uint32_t g_hsth[N_EDGES * 32];         // gathered h[src] as half2: [e][i/2]
__device__ uint4    g_bfrag[2 * NSLICE * FRAG_PER_SLICE]; // w2 (+bias) mma-fragment order
__device__ int      g_src[N_EDGES];
__device__ int      g_dst[N_EDGES];
__device__ int      g_bat[N_NODES];
__device__ float    g_hg[N_GRAPHS * HID];

// ---------------- aux stream/events (created at static-init; reused every call) ----------------
struct Aux {
    cudaStream_t s1;
    cudaEvent_t fork, join;
    Aux() {
        cudaStreamCreateWithFlags(&s1, cudaStreamNonBlocking);
        cudaEventCreateWithFlags(&fork, cudaEventDisableTiming);
        cudaEventCreateWithFlags(&join, cudaEventDisableTiming);
    }
};
static Aux g_aux;

__device__ __forceinline__ float lrelu(float v) { return v > 0.f ? v : 0.01f * v; }

// ---------------- PTX helpers ----------------
__device__ __forceinline__ void cp16(void* s, const void* g) {
    unsigned sa = (unsigned)__cvta_generic_to_shared(s);
    asm volatile("cp.async.cg.shared.global [%0], [%1], 16;" :: "r"(sa), "l"(g));
}
__device__ __forceinline__ void cp_commit() { asm volatile("cp.async.commit_group;"); }

// fp16 mma: D[16x8] += A[16x16] * B[16x8]
__device__ __forceinline__ void mma16(float* c, const uint32_t* a, uint32_t b0, uint32_t b1) {
    asm volatile(
        "mma.sync.aligned.m16n8k16.row.col.f32.f16.f16.f32 "
        "{%0,%1,%2,%3}, {%4,%5,%6,%7}, {%8,%9}, {%0,%1,%2,%3};"
        : "+f"(c[0]), "+f"(c[1]), "+f"(c[2]), "+f"(c[3])
        : "r"(a[0]), "r"(a[1]), "r"(a[2]), "r"(a[3]), "r"(b0), "r"(b1));
}

// vectorized global reduction (sm_90+)
__device__ __forceinline__ void red2(float* p, float x, float y) {
    asm volatile("red.global.add.v2.f32 [%0], {%1, %2};" :: "l"(p), "f"(x), "f"(y) : "memory");
}

// ---------------- index conversion (int64-vs-int32 auto-detect) + hg zero ----------------
__global__ void convert_idx_kernel(const void* ei, const void* bat) {
    __shared__ int s64;
    if (threadIdx.x == 0) {
        const unsigned* w = (const unsigned*)ei;
        int z = 0;
        for (int i = 1; i < 256; i += 2) z += (w[i] == 0u);
        s64 = (z > 64);
    }
    __syncthreads();
    const bool is64 = (s64 != 0);
    int stride = blockDim.x * gridDim.x;
    int gid = blockIdx.x * blockDim.x + threadIdx.x;
    for (int g = gid; g < N_EDGES; g += stride) {
        if (is64) {
            g_src[g] = (int)((const long long*)ei)[g];
            g_dst[g] = (int)((const long long*)ei)[N_EDGES + g];
        } else {
            g_src[g] = ((const int*)ei)[g];
            g_dst[g] = ((const int*)ei)[N_EDGES + g];
        }
    }
    for (int g = gid; g < N_NODES; g += stride) {
        g_bat[g] = is64 ? (int)((const long long*)bat)[g] : ((const int*)bat)[g];
    }
    if (gid < N_GRAPHS * HID) g_hg[gid] = 0.f;
}

// ---------------- node encoder: 32 nodes/CTA, item = (node, output-quad) ----------------
// static smem: xs 16384 + ws 32768 = 49152 B (exactly the 48KB static limit)
__global__ void __launch_bounds__(256) node_enc_kernel(
    const float* __restrict__ x, const float* __restrict__ w,
    const float* __restrict__ b, float* __restrict__ h) {
    __shared__ float xs[32 * 128];
    __shared__ float ws[128 * 64];
    const int tid = threadIdx.x;
    const int n0 = blockIdx.x * 32;

    for (int idx = tid; idx < 4096; idx += 256) {
        int n = n0 + (idx >> 7);
        xs[idx] = (n < N_NODES) ? x[(size_t)n * 128 + (idx & 127)] : 0.f;
    }
    for (int idx = tid; idx < 8192; idx += 256) ws[idx] = w[idx];
    __syncthreads();

#pragma unroll
    for (int q = 0; q < 2; ++q) {
        const int item = q * 256 + tid;          // 512 items = 32 nodes x 16 og
        const int og = item & 15, nl = item >> 4;
        const int n = n0 + nl;
        if (n < N_NODES) {
            float4 acc = *(const float4*)&b[4 * og];   // L1-cached broadcast
            const float* xr = xs + nl * 128;
#pragma unroll 16
            for (int i = 0; i < 128; ++i) {
                float v = xr[i];                           // warp: 2 addrs, broadcast
                float4 wv = *(const float4*)&ws[i * 64 + 4 * og];  // conflict-free LDS.128
                acc.x += v * wv.x; acc.y += v * wv.y;
                acc.z += v * wv.z; acc.w += v * wv.w;
            }
            float4 o;
            o.x = lrelu(acc.x); o.y = lrelu(acc.y);
            o.z = lrelu(acc.z); o.w = lrelu(acc.w);
            *(float4*)&h[(size_t)n * 64 + 4 * og] = o;
        }
    }
}

// ---------------- fused edge MLP (both layers): one thread per edge, broadcast weights ----------------
__global__ void __launch_bounds__(128) edge_mlp2_kernel(
    const float* __restrict__ ea,
    const float* __restrict__ w1a, const float* __restrict__ b1a,
    const float* __restrict__ w1b, const float* __restrict__ b1b,
    __half* __restrict__ tt1, __half* __restrict__ tt2) {
    __shared__ float eas[128 * 33];
    __shared__ float wA[32 * 64];
    __shared__ float wB[32 * 64];
    __shared__ float bA[64], bB[64];
    const int tid = threadIdx.x;
    const int tile = blockIdx.x;
    for (int idx = tid; idx < 128 * 32; idx += 128) {
        int e = idx >> 5, j = idx & 31;
        eas[e * 33 + j] = ea[tile * 4096 + idx];
    }
    for (int idx = tid; idx < 2048; idx += 128) { wA[idx] = w1a[idx]; wB[idx] = w1b[idx]; }
    if (tid < 64) { bA[tid] = b1a[tid]; bB[tid] = b1b[tid]; }
    __syncthreads();

    float ear[32];
#pragma unroll
    for (int j = 0; j < 32; ++j) ear[j] = eas[tid * 33 + j];

    __half* t1 = tt1 + tile * 8192 + tid;
    __half* t2 = tt2 + tile * 8192 + tid;
#pragma unroll 2
    for (int og = 0; og < 16; ++og) {
        float4 a1 = *(const float4*)&bA[4 * og];
        float4 a2 = *(const float4*)&bB[4 * og];
#pragma unroll
        for (int j = 0; j < 32; ++j) {
            float v = ear[j];
            float4 wa = *(const float4*)&wA[j * 64 + 4 * og];
            float4 wb = *(const float4*)&wB[j * 64 + 4 * og];
            a1.x += v * wa.x; a1.y += v * wa.y; a1.z += v * wa.z; a1.w += v * wa.w;
            a2.x += v * wb.x; a2.y += v * wb.y; a2.z += v * wb.z; a2.w += v * wb.w;
        }
        t1[(4 * og + 0) * 128] = __float2half(fmaxf(a1.x, 0.f));
        t1[(4 * og + 1) * 128] = __float2half(fmaxf(a1.y, 0.f));
        t1[(4 * og + 2) * 128] = __float2half(fmaxf(a1.z, 0.f));
        t1[(4 * og + 3) * 128] = __float2half(fmaxf(a1.w, 0.f));
        t2[(4 * og + 0) * 128] = __float2half(fmaxf(a2.x, 0.f));
        t2[(4 * og + 1) * 128] = __float2half(fmaxf(a2.y, 0.f));
        t2[(4 * og + 2) * 128] = __float2half(fmaxf(a2.z, 0.f));
        t2[(4 * og + 3) * 128] = __float2half(fmaxf(a2.w, 0.f));
    }
}

// ---------------- gather h[src] -> half2 [e][i/2]; also zeroes agg ----------------
__global__ void gather_kernel(const float* __restrict__ h, uint32_t* __restrict__ hsth,
                              float* __restrict__ agg) {
    int id = blockIdx.x * blockDim.x + threadIdx.x;  // < N_EDGES*32
    int p = id & 31;
    int e = id >> 5;
    float2 v = *(const float2*)(h + (size_t)g_src[e] * HID + 2 * p);
    __half2 hv = __floats2half2_rn(v.x, v.y);
    hsth[id] = *reinterpret_cast<uint32_t*>(&hv);
    if (id < N_NODES * HID) agg[id] = 0.f;
}

// ---------------- B prep (both layers): w2 (+b2) -> mma fragment order ----------------
__global__ void bprep2_kernel(const float* __restrict__ w2a, const float* __restrict__ b2a,
                              const float* __restrict__ w2b, const float* __restrict__ b2b,
                              uint4* __restrict__ bf) {
    int id = blockIdx.x * blockDim.x + threadIdx.x;  // < 2*65*512
    if (id >= 2 * NSLICE * FRAG_PER_SLICE) return;
    int layer = id >= NSLICE * FRAG_PER_SLICE;
    int rid = id - layer * NSLICE * FRAG_PER_SLICE;
    int s = rid >> 9;
    int f = rid & 511;
    int kt = f >> 7, np = (f >> 5) & 3, lane = f & 31;
    int tig = lane & 3, g = lane >> 2;
    const float* w2 = layer ? w2b : w2a;
    const float* b2 = layer ? b2b : b2a;
    int o0 = g + 16 * np, o1 = o0 + 8;
    int p0 = kt * 8 + tig, p1 = p0 + 4;
    auto rd = [&](int i, int o) -> float {
        return (s < 64) ? w2[(s << 12) + (i << 6) + o] : b2[(i << 6) + o];
    };
    auto pk = [&](int p, int o) -> uint32_t {
        __half2 hv = __floats2half2_rn(rd(2 * p, o), rd(2 * p + 1, o));
        return *reinterpret_cast<uint32_t*>(&hv);
    };
    uint4 v;
    v.x = pk(p0, o0); v.y = pk(p1, o0); v.z = pk(p0, o1); v.w = pk(p1, o1);
    bf[id] = v;
}

// ---------------- fp16 mma.sync message GEMM + scatter (256 edges / CTA, 8 warps) ----------------
__global__ void __launch_bounds__(256, 2) msg_mma_kernel(
    const __half* __restrict__ tt, const uint32_t* __restrict__ hsth,
    const uint4* __restrict__ bf, float* __restrict__ agg) {
    __shared__ uint4 Bs[2][FRAG_PER_SLICE];
    const int tid = threadIdx.x;
    const int w = tid >> 5, lane = tid & 31;
    const int g = lane >> 2, tig = lane & 3;
    const int subtile = 2 * blockIdx.x + (w >> 2);
    const int wl = w & 3;

    {
        cp16(&Bs[0][tid], bf + tid);
        cp16(&Bs[0][tid + 256], bf + tid + 256);
        cp_commit();
    }

    uint32_t hh[2][2][8];
    {
        const uint32_t* hb = hsth + ((size_t)subtile * 128 + wl * 32 + g) * 32 + tig;
#pragma unroll
        for (int m = 0; m < 2; ++m)
#pragma unroll
            for (int r = 0; r < 2; ++r) {
                const uint32_t* hp = hb + (m * 16 + r * 8) * 32;
#pragma unroll
                for (int j = 0; j < 8; ++j) hh[m][r][j] = hp[4 * j];
            }
    }

    float C[2][8][4];
#pragma unroll
    for (int m = 0; m < 2; ++m)
#pragma unroll
        for (int nt = 0; nt < 8; ++nt)
#pragma unroll
            for (int q = 0; q < 4; ++q) C[m][nt][q] = 0.f;

    const __half* tbase = tt + (size_t)subtile * 8192 + wl * 32 + g;

    for (int k = 0; k < NSLICE; ++k) {
        const int b = k & 1;
        asm volatile("cp.async.wait_group 0;");
        __syncthreads();
        if (k < NSLICE - 1) {
            const uint4* s = bf + (size_t)(k + 1) * FRAG_PER_SLICE;
            uint4* d = Bs[b ^ 1];
            cp16(&d[tid], s + tid);
            cp16(&d[tid + 256], s + tid + 256);
            cp_commit();
        }

        __half2 t2[4];
        if (k < 64) {
            const __half* tp = tbase + k * 128;
            t2[0] = __half2half2(tp[0]);
            t2[1] = __half2half2(tp[8]);
            t2[2] = __half2half2(tp[16]);
            t2[3] = __half2half2(tp[24]);
        } else {
            t2[0] = t2[1] = t2[2] = t2[3] = __float2half2_rn(1.f);
        }

        const uint4* B = Bs[b];
#pragma unroll
        for (int kt = 0; kt < 4; ++kt) {
            __half2 a[2][4];
#pragma unroll
            for (int m = 0; m < 2; ++m) {
                a[m][0] = __hmul2(*(const __half2*)&hh[m][0][2 * kt + 0], t2[2 * m + 0]);
                a[m][1] = __hmul2(*(const __half2*)&hh[m][1][2 * kt + 0], t2[2 * m + 1]);
                a[m][2] = __hmul2(*(const __half2*)&hh[m][0][2 * kt + 1], t2[2 * m + 0]);
                a[m][3] = __hmul2(*(const __half2*)&hh[m][1][2 * kt + 1], t2[2 * m + 1]);
            }
#pragma unroll
            for (int np = 0; np < 4; ++np) {
                uint4 bv = B[(kt * 4 + np) * 32 + lane];
                mma16(C[0][2 * np + 0], reinterpret_cast<const uint32_t*>(a[0]), bv.x, bv.y);
                mma16(C[1][2 * np + 0], reinterpret_cast<const uint32_t*>(a[1]), bv.x, bv.y);
                mma16(C[0][2 * np + 1], reinterpret_cast<const uint32_t*>(a[0]), bv.z, bv.w);
                mma16(C[1][2 * np + 1], reinterpret_cast<const uint32_t*>(a[1]), bv.z, bv.w);
            }
        }
    }

    const int ebase = subtile * 128 + wl * 32 + g;
#pragma unroll
    for (int m = 0; m < 2; ++m) {
        int d0 = g_dst[ebase + m * 16];
        int d1 = g_dst[ebase + m * 16 + 8];
        float* p0 = agg + (size_t)d0 * 64 + 2 * tig;
        float* p1 = agg + (size_t)d1 * 64 + 2 * tig;
#pragma unroll
        for (int nt = 0; nt < 8; ++nt) {
            red2(p0 + nt * 8, C[m][nt][0], C[m][nt][1]);
            red2(p1 + nt * 8, C[m][nt][2], C[m][nt][3]);
        }
    }
}

// ---------------- node update: thread-per-node, broadcast float4 root ----------------
__global__ void __launch_bounds__(128) node_update_kernel(
    const float* __restrict__ hin, const float* __restrict__ agg,
    const float* __restrict__ root, const float* __restrict__ bias,
    float* __restrict__ hout) {
    __shared__ float rs[64 * 64];
    __shared__ float bs[64];
    const int tid = threadIdx.x;
    for (int idx = tid; idx < 4096; idx += 128) rs[idx] = root[idx];
    if (tid < 64) bs[tid] = bias[tid];
    __syncthreads();

    const int n = blockIdx.x * 128 + tid;
    if (n >= N_NODES) return;

    const float* ap = agg + (size_t)n * 64;
    float4 acc[16];
#pragma unroll
    for (int og = 0; og < 16; ++og) {
        float4 a = *(const float4*)&ap[4 * og];
        const float4 bv = *(const float4*)&bs[4 * og];
        a.x += bv.x; a.y += bv.y; a.z += bv.z; a.w += bv.w;
        acc[og] = a;
    }

    const float* hp = hin + (size_t)n * 64;
#pragma unroll
    for (int ig = 0; ig < 4; ++ig) {
        float4 hv[4];
#pragma unroll
        for (int q = 0; q < 4; ++q) hv[q] = *(const float4*)&hp[ig * 16 + 4 * q];
        const float* hr = (const float*)hv;
#pragma unroll
        for (int j = 0; j < 16; ++j) {
            float v = hr[j];
            const float* rr = rs + (ig * 16 + j) * 64;
#pragma unroll
            for (int og = 0; og < 16; ++og) {
                float4 rv = *(const float4*)&rr[4 * og];
                acc[og].x += v * rv.x; acc[og].y += v * rv.y;
                acc[og].z += v * rv.z; acc[og].w += v * rv.w;
            }
        }
    }

    float* op = hout + (size_t)n * 64;
#pragma unroll
    for (int og = 0; og < 16; ++og) {
        float4 o;
        o.x = lrelu(acc[og].x); o.y = lrelu(acc[og].y);
        o.z = lrelu(acc[og].z); o.w = lrelu(acc[og].w);
        *(float4*)&op[4 * og] = o;
    }
}

// ---------------- global add pool (batch-sorted running-sum flush) ----------------
__global__ void pool_kernel(const float* __restrict__ h) {
    const int tid = threadIdx.x;
    const int o = tid & 63, q = tid >> 6;
    const int nbase = blockIdx.x * 256 + q * 64;
    float run = 0.f;
    int curb = -1;
    for (int j = 0; j < 64; ++j) {
        int n = nbase + j;
        if (n >= N_NODES) break;
        int bn = g_bat[n];
        if (bn != curb) {
            if (curb >= 0) atomicAdd(&g_hg[curb * 64 + o], run);
            run = 0.f;
            curb = bn;
        }
        run += h[(size_t)n * 64 + o];
    }
    if (curb >= 0) atomicAdd(&g_hg[curb * 64 + o], run);
}

// ---------------- readout head ----------------
__global__ void head_kernel(const float* __restrict__ fc1w, const float* __restrict__ fc1b,
                            const float* __restrict__ fc2w, const float* __restrict__ fc2b,
                            float* __restrict__ out) {
    __shared__ float hs[N_GRAPHS * HID];
    int g = threadIdx.x;
    for (int i = g; i < N_GRAPHS * HID; i += 64) hs[i] = g_hg[i];
    __syncthreads();
    float acc = fc2b[0];
#pragma unroll 4
    for (int j = 0; j < 32; ++j) {
        float s = fc1b[j];
#pragma unroll 8
        for (int i = 0; i < 64; ++i) s += hs[g * 64 + i] * fc1w[i * 32 + j];
        acc += lrelu(s) * fc2w[j];
    }
    out[g] = acc;
}

// ---------------- launch ----------------
extern "C" void kernel_launch(void* const* d_in, const int* in_sizes, int n_in,
                              void* d_out, int out_size) {
    const float* x     = (const float*)d_in[0];
    const void*  ei    = d_in[1];
    const float* ea    = (const float*)d_in[2];
    const void*  bat   = d_in[3];
    const float* nfc_w = (const float*)d_in[4];
    const float* nfc_b = (const float*)d_in[5];
    const float* e1w1  = (const float*)d_in[6];
    const float* e1b1  = (const float*)d_in[7];
    const float* e1w2  = (const float*)d_in[8];
    const float* e1b2  = (const float*)d_in[9];
    const float* root1 = (const float*)d_in[10];
    const float* bias1 = (const float*)d_in[11];
    const float* e2w1  = (const float*)d_in[12];
    const float* e2b1  = (const float*)d_in[13];
    const float* e2w2  = (const float*)d_in[14];
    const float* e2b2  = (const float*)d_in[15];
    const float* root2 = (const float*)d_in[16];
    const float* bias2 = (const float*)d_in[17];
    const float* fc1w  = (const float*)d_in[18];
    const float* fc1b  = (const float*)d_in[19];
    const float* fc2w  = (const float*)d_in[20];
    const float* fc2b  = (const float*)d_in[21];
    float* out = (float*)d_out;

    float *h0, *h1, *agg, *hg;
    __half *tt1, *tt2;
    uint32_t* hsth;
    uint4* bfp;
    cudaGetSymbolAddress((void**)&h0, g_h0);
    cudaGetSymbolAddress((void**)&h1, g_h1);
    cudaGetSymbolAddress((void**)&agg, g_agg);
    cudaGetSymbolAddress((void**)&tt1, g_tt1);
    cudaGetSymbolAddress((void**)&tt2, g_tt2);
    cudaGetSymbolAddress((void**)&hg, g_hg);
    cudaGetSymbolAddress((void**)&hsth, g_hsth);
    cudaGetSymbolAddress((void**)&bfp, g_bfrag);

    // fork: edge MLP + weight prep on aux stream, node path on main stream
    cudaEventRecord(g_aux.fork, 0);
    cudaStreamWaitEvent(g_aux.s1, g_aux.fork, 0);
    edge_mlp2_kernel<<<NTILES, 128, 0, g_aux.s1>>>(ea, e1w1, e1b1, e2w1, e2b1, tt1, tt2);
    bprep2_kernel<<<(2 * NSLICE * FRAG_PER_SLICE + 255) / 256, 256, 0, g_aux.s1>>>(
        e1w2, e1b2, e2w2, e2b2, bfp);
    cudaEventRecord(g_aux.join, g_aux.s1);

    convert_idx_kernel<<<256, 256>>>(ei, bat);
    node_enc_kernel<<<(N_NODES + 31) / 32, 256>>>(x, nfc_w, nfc_b, h0);
    gather_kernel<<<N_EDGES * 32 / 256, 256>>>(h0, hsth, agg);

    cudaStreamWaitEvent(0, g_aux.join, 0);

    // layer 1
    msg_mma_kernel<<<NTILES / 2, 256>>>(tt1, hsth, bfp, agg);
    node_update_kernel<<<(N_NODES + 127) / 128, 128>>>(h0, agg, root1, bias1, h1);

    // layer 2
    gather_kernel<<<N_EDGES * 32 / 256, 256>>>(h1, hsth, agg);
    msg_mma_kernel<<<NTILES / 2, 256>>>(tt2, hsth, bfp + (size_t)NSLICE * FRAG_PER_SLICE, agg);
    node_update_kernel<<<(N_NODES + 127) / 128, 128>>>(h1, agg, root2, bias2, h0);

    // pool + head
    pool_kernel<<<(N_NODES + 255) / 256, 256>>>(h0);
    head_kernel<<<1, 64>>>(fc1w, fc1b, fc2w, fc2b, out);
}

// round 13
// speedup vs baseline: 1.0616x; 1.0360x over previous
#include <cuda_runtime.h>
#include <cuda_bf16.h>
#include <cuda_fp16.h>
#include <cstdint>

#define N_NODES 10000
#define N_EDGES 64000
#define N_GRAPHS 64
#define HID 64
#define ET 128                    // edges per GEMM subtile
#define NTILES (N_EDGES / ET)     // 500 subtiles; 250 CTAs x 2
#define NSLICE 65                 // 64 w2 slices + 1 bias slice
#define FRAG_PER_SLICE 512        // 4 kt x 4 np x 32 lanes, uint4 each = 8KB

// ---------------- scratch (device globals; no allocation allowed) ----------------
__device__ float    g_h0[N_NODES * HID];
__device__ float    g_h1[N_NODES * HID];
__device__ float    g_agg[N_NODES * HID];
__device__ __half   g_tt1[NTILES * HID * ET];     // edge-MLP layer1 (fp16): [subtile][k][e]
__device__ __half   g_tt2[NTILES * HID * ET];     // edge-MLP layer2 (fp16): [subtile][k][e]
__device__ uint32_t g_hc[N_NODES * 32];           // fp16 copy of current h: [n][i/2]
__device__ uint4    g_bfrag[2 * NSLICE * FRAG_PER_SLICE]; // w2 (+bias) mma-fragment order
__device__ int      g_src[N_EDGES];
__device__ int      g_dst[N_EDGES];
__device__ int      g_bat[N_NODES];
__device__ float    g_hg[N_GRAPHS * HID];

// ---------------- aux stream/events (created at static-init; reused every call) ----------------
struct Aux {
    cudaStream_t s1;
    cudaEvent_t fork, join;
    Aux() {
        cudaStreamCreateWithFlags(&s1, cudaStreamNonBlocking);
        cudaEventCreateWithFlags(&fork, cudaEventDisableTiming);
        cudaEventCreateWithFlags(&join, cudaEventDisableTiming);
    }
};
static Aux g_aux;

__device__ __forceinline__ float lrelu(float v) { return v > 0.f ? v : 0.01f * v; }

// ---------------- PTX helpers ----------------
__device__ __forceinline__ void cp16(void* s, const void* g) {
    unsigned sa = (unsigned)__cvta_generic_to_shared(s);
    asm volatile("cp.async.cg.shared.global [%0], [%1], 16;" :: "r"(sa), "l"(g));
}
__device__ __forceinline__ void cp_commit() { asm volatile("cp.async.commit_group;"); }

// fp16 mma: D[16x8] += A[16x16] * B[16x8]
__device__ __forceinline__ void mma16(float* c, const uint32_t* a, uint32_t b0, uint32_t b1) {
    asm volatile(
        "mma.sync.aligned.m16n8k16.row.col.f32.f16.f16.f32 "
        "{%0,%1,%2,%3}, {%4,%5,%6,%7}, {%8,%9}, {%0,%1,%2,%3};"
        : "+f"(c[0]), "+f"(c[1]), "+f"(c[2]), "+f"(c[3])
        : "r"(a[0]), "r"(a[1]), "r"(a[2]), "r"(a[3]), "r"(b0), "r"(b1));
}

// vectorized global reduction (sm_90+)
__device__ __forceinline__ void red2(float* p, float x, float y) {
    asm volatile("red.global.add.v2.f32 [%0], {%1, %2};" :: "l"(p), "f"(x), "f"(y) : "memory");
}

__device__ __forceinline__ uint32_t pack_h2(float a, float b) {
    __half2 hv = __floats2half2_rn(a, b);
    return *reinterpret_cast<uint32_t*>(&hv);
}

// ---------------- index conversion (int64-vs-int32 auto-detect) + hg zero ----------------
__global__ void convert_idx_kernel(const void* ei, const void* bat) {
    __shared__ int s64;
    if (threadIdx.x == 0) {
        const unsigned* w = (const unsigned*)ei;
        int z = 0;
        for (int i = 1; i < 256; i += 2) z += (w[i] == 0u);
        s64 = (z > 64);
    }
    __syncthreads();
    const bool is64 = (s64 != 0);
    int stride = blockDim.x * gridDim.x;
    int gid = blockIdx.x * blockDim.x + threadIdx.x;
    for (int g = gid; g < N_EDGES; g += stride) {
        if (is64) {
            g_src[g] = (int)((const long long*)ei)[g];
            g_dst[g] = (int)((const long long*)ei)[N_EDGES + g];
        } else {
            g_src[g] = ((const int*)ei)[g];
            g_dst[g] = ((const int*)ei)[N_EDGES + g];
        }
    }
    for (int g = gid; g < N_NODES; g += stride) {
        g_bat[g] = is64 ? (int)((const long long*)bat)[g] : ((const int*)bat)[g];
    }
    if (gid < N_GRAPHS * HID) g_hg[gid] = 0.f;
}

// ---------------- node encoder: 32 nodes/CTA, item-pair shares og ----------------
// also emits fp16 h copy and zeroes agg
__global__ void __launch_bounds__(256) node_enc_kernel(
    const float* __restrict__ x, const float* __restrict__ w,
    const float* __restrict__ b, float* __restrict__ h,
    uint32_t* __restrict__ hc, float* __restrict__ agg) {
    __shared__ float xs[32 * 128];
    __shared__ float ws[128 * 64];
    const int tid = threadIdx.x;
    const int n0 = blockIdx.x * 32;

    for (int idx = tid; idx < 4096; idx += 256) {
        int n = n0 + (idx >> 7);
        xs[idx] = (n < N_NODES) ? x[(size_t)n * 128 + (idx & 127)] : 0.f;
    }
    for (int idx = tid; idx < 8192; idx += 256) ws[idx] = w[idx];
    __syncthreads();

    const int og = tid & 15, nl = tid >> 4;      // nl in 0..15; pair handles nl and nl+16
    const int na = n0 + nl, nb = n0 + nl + 16;
    float4 A = *(const float4*)&b[4 * og];
    float4 B = A;
    const float* xa = xs + nl * 128;
    const float* xb = xs + (nl + 16) * 128;
#pragma unroll 16
    for (int i = 0; i < 128; ++i) {
        float va = xa[i], vb = xb[i];
        float4 wv = *(const float4*)&ws[i * 64 + 4 * og];  // shared LDS.128
        A.x += va * wv.x; A.y += va * wv.y; A.z += va * wv.z; A.w += va * wv.w;
        B.x += vb * wv.x; B.y += vb * wv.y; B.z += vb * wv.z; B.w += vb * wv.w;
    }
    if (na < N_NODES) {
        float4 o;
        o.x = lrelu(A.x); o.y = lrelu(A.y); o.z = lrelu(A.z); o.w = lrelu(A.w);
        *(float4*)&h[(size_t)na * 64 + 4 * og] = o;
        hc[(size_t)na * 32 + 2 * og] = pack_h2(o.x, o.y);
        hc[(size_t)na * 32 + 2 * og + 1] = pack_h2(o.z, o.w);
        *(float4*)&agg[(size_t)na * 64 + 4 * og] = make_float4(0.f, 0.f, 0.f, 0.f);
    }
    if (nb < N_NODES) {
        float4 o;
        o.x = lrelu(B.x); o.y = lrelu(B.y); o.z = lrelu(B.z); o.w = lrelu(B.w);
        *(float4*)&h[(size_t)nb * 64 + 4 * og] = o;
        hc[(size_t)nb * 32 + 2 * og] = pack_h2(o.x, o.y);
        hc[(size_t)nb * 32 + 2 * og + 1] = pack_h2(o.z, o.w);
        *(float4*)&agg[(size_t)nb * 64 + 4 * og] = make_float4(0.f, 0.f, 0.f, 0.f);
    }
}

// ---------------- fused edge MLP (both layers): one thread per edge, broadcast weights ----------------
__global__ void __launch_bounds__(128) edge_mlp2_kernel(
    const float* __restrict__ ea,
    const float* __restrict__ w1a, const float* __restrict__ b1a,
    const float* __restrict__ w1b, const float* __restrict__ b1b,
    __half* __restrict__ tt1, __half* __restrict__ tt2) {
    __shared__ float eas[128 * 33];
    __shared__ float wA[32 * 64];
    __shared__ float wB[32 * 64];
    __shared__ float bA[64], bB[64];
    const int tid = threadIdx.x;
    const int tile = blockIdx.x;
    for (int idx = tid; idx < 128 * 32; idx += 128) {
        int e = idx >> 5, j = idx & 31;
        eas[e * 33 + j] = ea[tile * 4096 + idx];
    }
    for (int idx = tid; idx < 2048; idx += 128) { wA[idx] = w1a[idx]; wB[idx] = w1b[idx]; }
    if (tid < 64) { bA[tid] = b1a[tid]; bB[tid] = b1b[tid]; }
    __syncthreads();

    float ear[32];
#pragma unroll
    for (int j = 0; j < 32; ++j) ear[j] = eas[tid * 33 + j];

    __half* t1 = tt1 + tile * 8192 + tid;
    __half* t2 = tt2 + tile * 8192 + tid;
#pragma unroll 2
    for (int og = 0; og < 16; ++og) {
        float4 a1 = *(const float4*)&bA[4 * og];
        float4 a2 = *(const float4*)&bB[4 * og];
#pragma unroll
        for (int j = 0; j < 32; ++j) {
            float v = ear[j];
            float4 wa = *(const float4*)&wA[j * 64 + 4 * og];
            float4 wb = *(const float4*)&wB[j * 64 + 4 * og];
            a1.x += v * wa.x; a1.y += v * wa.y; a1.z += v * wa.z; a1.w += v * wa.w;
            a2.x += v * wb.x; a2.y += v * wb.y; a2.z += v * wb.z; a2.w += v * wb.w;
        }
        t1[(4 * og + 0) * 128] = __float2half(fmaxf(a1.x, 0.f));
        t1[(4 * og + 1) * 128] = __float2half(fmaxf(a1.y, 0.f));
        t1[(4 * og + 2) * 128] = __float2half(fmaxf(a1.z, 0.f));
        t1[(4 * og + 3) * 128] = __float2half(fmaxf(a1.w, 0.f));
        t2[(4 * og + 0) * 128] = __float2half(fmaxf(a2.x, 0.f));
        t2[(4 * og + 1) * 128] = __float2half(fmaxf(a2.y, 0.f));
        t2[(4 * og + 2) * 128] = __float2half(fmaxf(a2.z, 0.f));
        t2[(4 * og + 3) * 128] = __float2half(fmaxf(a2.w, 0.f));
    }
}

// ---------------- B prep (both layers): w2 (+b2) -> mma fragment order ----------------
__global__ void bprep2_kernel(const float* __restrict__ w2a, const float* __restrict__ b2a,
                              const float* __restrict__ w2b, const float* __restrict__ b2b,
                              uint4* __restrict__ bf) {
    int id = blockIdx.x * blockDim.x + threadIdx.x;  // < 2*65*512
    if (id >= 2 * NSLICE * FRAG_PER_SLICE) return;
    int layer = id >= NSLICE * FRAG_PER_SLICE;
    int rid = id - layer * NSLICE * FRAG_PER_SLICE;
    int s = rid >> 9;
    int f = rid & 511;
    int kt = f >> 7, np = (f >> 5) & 3, lane = f & 31;
    int tig = lane & 3, g = lane >> 2;
    const float* w2 = layer ? w2b : w2a;
    const float* b2 = layer ? b2b : b2a;
    int o0 = g + 16 * np, o1 = o0 + 8;
    int p0 = kt * 8 + tig, p1 = p0 + 4;
    auto rd = [&](int i, int o) -> float {
        return (s < 64) ? w2[(s << 12) + (i << 6) + o] : b2[(i << 6) + o];
    };
    auto pk = [&](int p, int o) -> uint32_t {
        return pack_h2(rd(2 * p, o), rd(2 * p + 1, o));
    };
    uint4 v;
    v.x = pk(p0, o0); v.y = pk(p1, o0); v.z = pk(p0, o1); v.w = pk(p1, o1);
    bf[id] = v;
}

// ---------------- fp16 mma.sync message GEMM + direct gather + scatter ----------------
__global__ void __launch_bounds__(256, 2) msg_mma_kernel(
    const __half* __restrict__ tt, const uint32_t* __restrict__ hc,
    const uint4* __restrict__ bf, float* __restrict__ agg) {
    __shared__ uint4 Bs[2][FRAG_PER_SLICE];
    const int tid = threadIdx.x;
    const int w = tid >> 5, lane = tid & 31;
    const int g = lane >> 2, tig = lane & 3;
    const int subtile = 2 * blockIdx.x + (w >> 2);
    const int wl = w & 3;

    {
        cp16(&Bs[0][tid], bf + tid);
        cp16(&Bs[0][tid + 256], bf + tid + 256);
        cp_commit();
    }

    // direct gather: hh[m][r][j] = hc[src[e(m,r)]][tig + 4j]
    const int ebase = subtile * 128 + wl * 32 + g;
    uint32_t hh[2][2][8];
#pragma unroll
    for (int m = 0; m < 2; ++m)
#pragma unroll
        for (int r = 0; r < 2; ++r) {
            const int e = ebase + m * 16 + r * 8;
            const uint32_t* hp = hc + (size_t)g_src[e] * 32 + tig;
#pragma unroll
            for (int j = 0; j < 8; ++j) hh[m][r][j] = hp[4 * j];
        }

    float C[2][8][4];
#pragma unroll
    for (int m = 0; m < 2; ++m)
#pragma unroll
        for (int nt = 0; nt < 8; ++nt)
#pragma unroll
            for (int q = 0; q < 4; ++q) C[m][nt][q] = 0.f;

    const __half* tbase = tt + (size_t)subtile * 8192 + wl * 32 + g;

    for (int k = 0; k < NSLICE; ++k) {
        const int b = k & 1;
        asm volatile("cp.async.wait_group 0;");
        __syncthreads();
        if (k < NSLICE - 1) {
            const uint4* s = bf + (size_t)(k + 1) * FRAG_PER_SLICE;
            uint4* d = Bs[b ^ 1];
            cp16(&d[tid], s + tid);
            cp16(&d[tid + 256], s + tid + 256);
            cp_commit();
        }

        __half2 t2[4];
        if (k < 64) {
            const __half* tp = tbase + k * 128;
            t2[0] = __half2half2(tp[0]);
            t2[1] = __half2half2(tp[8]);
            t2[2] = __half2half2(tp[16]);
            t2[3] = __half2half2(tp[24]);
        } else {
            t2[0] = t2[1] = t2[2] = t2[3] = __float2half2_rn(1.f);
        }

        const uint4* B = Bs[b];
#pragma unroll
        for (int kt = 0; kt < 4; ++kt) {
            __half2 a[2][4];
#pragma unroll
            for (int m = 0; m < 2; ++m) {
                a[m][0] = __hmul2(*(const __half2*)&hh[m][0][2 * kt + 0], t2[2 * m + 0]);
                a[m][1] = __hmul2(*(const __half2*)&hh[m][1][2 * kt + 0], t2[2 * m + 1]);
                a[m][2] = __hmul2(*(const __half2*)&hh[m][0][2 * kt + 1], t2[2 * m + 0]);
                a[m][3] = __hmul2(*(const __half2*)&hh[m][1][2 * kt + 1], t2[2 * m + 1]);
            }
#pragma unroll
            for (int np = 0; np < 4; ++np) {
                uint4 bv = B[(kt * 4 + np) * 32 + lane];
                mma16(C[0][2 * np + 0], reinterpret_cast<const uint32_t*>(a[0]), bv.x, bv.y);
                mma16(C[1][2 * np + 0], reinterpret_cast<const uint32_t*>(a[1]), bv.x, bv.y);
                mma16(C[0][2 * np + 1], reinterpret_cast<const uint32_t*>(a[0]), bv.z, bv.w);
                mma16(C[1][2 * np + 1], reinterpret_cast<const uint32_t*>(a[1]), bv.z, bv.w);
            }
        }
    }

#pragma unroll
    for (int m = 0; m < 2; ++m) {
        int d0 = g_dst[ebase + m * 16];
        int d1 = g_dst[ebase + m * 16 + 8];
        float* p0 = agg + (size_t)d0 * 64 + 2 * tig;
        float* p1 = agg + (size_t)d1 * 64 + 2 * tig;
#pragma unroll
        for (int nt = 0; nt < 8; ++nt) {
            red2(p0 + nt * 8, C[m][nt][0], C[m][nt][1]);
            red2(p1 + nt * 8, C[m][nt][2], C[m][nt][3]);
        }
    }
}

// ---------------- node update: thread-per-node; emits fp16 copy; zeroes agg ----------------
__global__ void __launch_bounds__(128) node_update_kernel(
    const float* __restrict__ hin, float* __restrict__ agg,
    const float* __restrict__ root, const float* __restrict__ bias,
    float* __restrict__ hout, uint32_t* __restrict__ hc) {
    __shared__ float rs[64 * 64];
    __shared__ float bs[64];
    const int tid = threadIdx.x;
    for (int idx = tid; idx < 4096; idx += 128) rs[idx] = root[idx];
    if (tid < 64) bs[tid] = bias[tid];
    __syncthreads();

    const int n = blockIdx.x * 128 + tid;
    if (n >= N_NODES) return;

    float* ap = agg + (size_t)n * 64;
    float4 acc[16];
#pragma unroll
    for (int og = 0; og < 16; ++og) {
        float4 a = *(const float4*)&ap[4 * og];
        const float4 bv = *(const float4*)&bs[4 * og];
        a.x += bv.x; a.y += bv.y; a.z += bv.z; a.w += bv.w;
        acc[og] = a;
    }
    // zero agg for the next layer's scatter (this thread owns the whole row)
#pragma unroll
    for (int og = 0; og < 16; ++og)
        *(float4*)&ap[4 * og] = make_float4(0.f, 0.f, 0.f, 0.f);

    const float* hp = hin + (size_t)n * 64;
#pragma unroll
    for (int ig = 0; ig < 4; ++ig) {
        float4 hv[4];
#pragma unroll
        for (int q = 0; q < 4; ++q) hv[q] = *(const float4*)&hp[ig * 16 + 4 * q];
        const float* hr = (const float*)hv;
#pragma unroll
        for (int j = 0; j < 16; ++j) {
            float v = hr[j];
            const float* rr = rs + (ig * 16 + j) * 64;
#pragma unroll
            for (int og = 0; og < 16; ++og) {
                float4 rv = *(const float4*)&rr[4 * og];
                acc[og].x += v * rv.x; acc[og].y += v * rv.y;
                acc[og].z += v * rv.z; acc[og].w += v * rv.w;
            }
        }
    }

    float* op = hout + (size_t)n * 64;
    uint32_t* hcp = hc + (size_t)n * 32;
#pragma unroll
    for (int og = 0; og < 16; ++og) {
        float4 o;
        o.x = lrelu(acc[og].x); o.y = lrelu(acc[og].y);
        o.z = lrelu(acc[og].z); o.w = lrelu(acc[og].w);
        *(float4*)&op[4 * og] = o;
        hcp[2 * og] = pack_h2(o.x, o.y);
        hcp[2 * og + 1] = pack_h2(o.z, o.w);
    }
}

// ---------------- global add pool (batch-sorted running-sum flush) ----------------
__global__ void pool_kernel(const float* __restrict__ h) {
    const int tid = threadIdx.x;
    const int o = tid & 63, q = tid >> 6;
    const int nbase = blockIdx.x * 256 + q * 64;
    float run = 0.f;
    int curb = -1;
    for (int j = 0; j < 64; ++j) {
        int n = nbase + j;
        if (n >= N_NODES) break;
        int bn = g_bat[n];
        if (bn != curb) {
            if (curb >= 0) atomicAdd(&g_hg[curb * 64 + o], run);
            run = 0.f;
            curb = bn;
        }
        run += h[(size_t)n * 64 + o];
    }
    if (curb >= 0) atomicAdd(&g_hg[curb * 64 + o], run);
}

// ---------------- readout head ----------------
__global__ void head_kernel(const float* __restrict__ fc1w, const float* __restrict__ fc1b,
                            const float* __restrict__ fc2w, const float* __restrict__ fc2b,
                            float* __restrict__ out) {
    __shared__ float hs[N_GRAPHS * HID];
    int g = threadIdx.x;
    for (int i = g; i < N_GRAPHS * HID; i += 64) hs[i] = g_hg[i];
    __syncthreads();
    float acc = fc2b[0];
#pragma unroll 4
    for (int j = 0; j < 32; ++j) {
        float s = fc1b[j];
#pragma unroll 8
        for (int i = 0; i < 64; ++i) s += hs[g * 64 + i] * fc1w[i * 32 + j];
        acc += lrelu(s) * fc2w[j];
    }
    out[g] = acc;
}

// ---------------- launch ----------------
extern "C" void kernel_launch(void* const* d_in, const int* in_sizes, int n_in,
                              void* d_out, int out_size) {
    const float* x     = (const float*)d_in[0];
    const void*  ei    = d_in[1];
    const float* ea    = (const float*)d_in[2];
    const void*  bat   = d_in[3];
    const float* nfc_w = (const float*)d_in[4];
    const float* nfc_b = (const float*)d_in[5];
    const float* e1w1  = (const float*)d_in[6];
    const float* e1b1  = (const float*)d_in[7];
    const float* e1w2  = (const float*)d_in[8];
    const float* e1b2  = (const float*)d_in[9];
    const float* root1 = (const float*)d_in[10];
    const float* bias1 = (const float*)d_in[11];
    const float* e2w1  = (const float*)d_in[12];
    const float* e2b1  = (const float*)d_in[13];
    const float* e2w2  = (const float*)d_in[14];
    const float* e2b2  = (const float*)d_in[15];
    const float* root2 = (const float*)d_in[16];
    const float* bias2 = (const float*)d_in[17];
    const float* fc1w  = (const float*)d_in[18];
    const float* fc1b  = (const float*)d_in[19];
    const float* fc2w  = (const float*)d_in[20];
    const float* fc2b  = (const float*)d_in[21];
    float* out = (float*)d_out;

    float *h0, *h1, *agg, *hg;
    __half *tt1, *tt2;
    uint32_t* hc;
    uint4* bfp;
    cudaGetSymbolAddress((void**)&h0, g_h0);
    cudaGetSymbolAddress((void**)&h1, g_h1);
    cudaGetSymbolAddress((void**)&agg, g_agg);
    cudaGetSymbolAddress((void**)&tt1, g_tt1);
    cudaGetSymbolAddress((void**)&tt2, g_tt2);
    cudaGetSymbolAddress((void**)&hg, g_hg);
    cudaGetSymbolAddress((void**)&hc, g_hc);
    cudaGetSymbolAddress((void**)&bfp, g_bfrag);

    // fork: edge MLP + weight prep + index convert on aux stream; node encoder on main
    cudaEventRecord(g_aux.fork, 0);
    cudaStreamWaitEvent(g_aux.s1, g_aux.fork, 0);
    edge_mlp2_kernel<<<NTILES, 128, 0, g_aux.s1>>>(ea, e1w1, e1b1, e2w1, e2b1, tt1, tt2);
    bprep2_kernel<<<(2 * NSLICE * FRAG_PER_SLICE + 255) / 256, 256, 0, g_aux.s1>>>(
        e1w2, e1b2, e2w2, e2b2, bfp);
    convert_idx_kernel<<<256, 256, 0, g_aux.s1>>>(ei, bat);
    cudaEventRecord(g_aux.join, g_aux.s1);

    node_enc_kernel<<<(N_NODES + 31) / 32, 256>>>(x, nfc_w, nfc_b, h0, hc, agg);

    cudaStreamWaitEvent(0, g_aux.join, 0);

    // layer 1
    msg_mma_kernel<<<NTILES / 2, 256>>>(tt1, hc, bfp, agg);
    node_update_kernel<<<(N_NODES + 127) / 128, 128>>>(h0, agg, root1, bias1, h1, hc);

    // layer 2
    msg_mma_kernel<<<NTILES / 2, 256>>>(tt2, hc, bfp + (size_t)NSLICE * FRAG_PER_SLICE, agg);
    node_update_kernel<<<(N_NODES + 127) / 128, 128>>>(h1, agg, root2, bias2, h0, hc);

    // pool + head
    pool_kernel<<<(N_NODES + 255) / 256, 256>>>(h0);
    head_kernel<<<1, 64>>>(fc1w, fc1b, fc2w, fc2b, out);
}

// round 14
// speedup vs baseline: 1.1176x; 1.0528x over previous
#include <cuda_runtime.h>
#include <cuda_bf16.h>
#include <cuda_fp16.h>
#include <cstdint>

#define N_NODES 10000
#define N_EDGES 64000
#define N_GRAPHS 64
#define HID 64
#define ET 128                    // edges per GEMM subtile
#define NTILES (N_EDGES / ET)     // 500 subtiles; 250 CTAs x 2
#define NSLICE 65                 // 64 w2 slices + 1 bias slice
#define FRAG_PER_SLICE 512        // 4 kt x 4 np x 32 lanes, uint4 each = 8KB

// ---------------- scratch (device globals; no allocation allowed) ----------------
__device__ float    g_h0[N_NODES * HID];
__device__ float    g_h1[N_NODES * HID];
__device__ float    g_agg[N_NODES * HID];
__device__ __half   g_tt1[NTILES * HID * ET];     // edge-MLP layer1 (fp16): [subtile][k][e]
__device__ __half   g_tt2[NTILES * HID * ET];     // edge-MLP layer2 (fp16): [subtile][k][e]
__device__ uint32_t g_hc[N_NODES * 32];           // fp16 copy of current h: [n][i/2]
__device__ uint4    g_bfrag[2 * NSLICE * FRAG_PER_SLICE]; // w2 (+bias) mma-fragment order
__device__ int      g_src[N_EDGES];
__device__ int      g_dst[N_EDGES];
__device__ int      g_bat[N_NODES];
__device__ float    g_hg[N_GRAPHS * HID];

// ---------------- aux stream/events (created at static-init; reused every call) ----------------
struct Aux {
    cudaStream_t s1;
    cudaEvent_t fork, join;
    Aux() {
        cudaStreamCreateWithFlags(&s1, cudaStreamNonBlocking);
        cudaEventCreateWithFlags(&fork, cudaEventDisableTiming);
        cudaEventCreateWithFlags(&join, cudaEventDisableTiming);
    }
};
static Aux g_aux;

__device__ __forceinline__ float lrelu(float v) { return v > 0.f ? v : 0.01f * v; }

// ---------------- PTX helpers ----------------
__device__ __forceinline__ void cp16(void* s, const void* g) {
    unsigned sa = (unsigned)__cvta_generic_to_shared(s);
    asm volatile("cp.async.cg.shared.global [%0], [%1], 16;" :: "r"(sa), "l"(g));
}
__device__ __forceinline__ void cp_commit() { asm volatile("cp.async.commit_group;"); }

// fp16 mma: D[16x8] += A[16x16] * B[16x8]
__device__ __forceinline__ void mma16(float* c, const uint32_t* a, uint32_t b0, uint32_t b1) {
    asm volatile(
        "mma.sync.aligned.m16n8k16.row.col.f32.f16.f16.f32 "
        "{%0,%1,%2,%3}, {%4,%5,%6,%7}, {%8,%9}, {%0,%1,%2,%3};"
        : "+f"(c[0]), "+f"(c[1]), "+f"(c[2]), "+f"(c[3])
        : "r"(a[0]), "r"(a[1]), "r"(a[2]), "r"(a[3]), "r"(b0), "r"(b1));
}

// vectorized global reduction (sm_90+)
__device__ __forceinline__ void red2(float* p, float x, float y) {
    asm volatile("red.global.add.v2.f32 [%0], {%1, %2};" :: "l"(p), "f"(x), "f"(y) : "memory");
}

__device__ __forceinline__ uint32_t pack_h2(float a, float b) {
    __half2 hv = __floats2half2_rn(a, b);
    return *reinterpret_cast<uint32_t*>(&hv);
}

// ---------------- index conversion (int64-vs-int32 auto-detect) + hg zero ----------------
__global__ void convert_idx_kernel(const void* ei, const void* bat) {
    __shared__ int s64;
    if (threadIdx.x == 0) {
        const unsigned* w = (const unsigned*)ei;
        int z = 0;
        for (int i = 1; i < 256; i += 2) z += (w[i] == 0u);
        s64 = (z > 64);
    }
    __syncthreads();
    const bool is64 = (s64 != 0);
    int stride = blockDim.x * gridDim.x;
    int gid = blockIdx.x * blockDim.x + threadIdx.x;
    for (int g = gid; g < N_EDGES; g += stride) {
        if (is64) {
            g_src[g] = (int)((const long long*)ei)[g];
            g_dst[g] = (int)((const long long*)ei)[N_EDGES + g];
        } else {
            g_src[g] = ((const int*)ei)[g];
            g_dst[g] = ((const int*)ei)[N_EDGES + g];
        }
    }
    for (int g = gid; g < N_NODES; g += stride) {
        g_bat[g] = is64 ? (int)((const long long*)bat)[g] : ((const int*)bat)[g];
    }
    if (gid < N_GRAPHS * HID) g_hg[gid] = 0.f;
}

// ---------------- node encoder: 32 nodes/CTA, item-pair shares og ----------------
// also emits fp16 h copy and zeroes agg
__global__ void __launch_bounds__(256) node_enc_kernel(
    const float* __restrict__ x, const float* __restrict__ w,
    const float* __restrict__ b, float* __restrict__ h,
    uint32_t* __restrict__ hc, float* __restrict__ agg) {
    __shared__ float xs[32 * 128];
    __shared__ float ws[128 * 64];
    const int tid = threadIdx.x;
    const int n0 = blockIdx.x * 32;

    for (int idx = tid; idx < 4096; idx += 256) {
        int n = n0 + (idx >> 7);
        xs[idx] = (n < N_NODES) ? x[(size_t)n * 128 + (idx & 127)] : 0.f;
    }
    for (int idx = tid; idx < 8192; idx += 256) ws[idx] = w[idx];
    __syncthreads();

    const int og = tid & 15, nl = tid >> 4;      // nl in 0..15; pair handles nl and nl+16
    const int na = n0 + nl, nb = n0 + nl + 16;
    float4 A = *(const float4*)&b[4 * og];
    float4 B = A;
    const float* xa = xs + nl * 128;
    const float* xb = xs + (nl + 16) * 128;
#pragma unroll 16
    for (int i = 0; i < 128; ++i) {
        float va = xa[i], vb = xb[i];
        float4 wv = *(const float4*)&ws[i * 64 + 4 * og];  // shared LDS.128
        A.x += va * wv.x; A.y += va * wv.y; A.z += va * wv.z; A.w += va * wv.w;
        B.x += vb * wv.x; B.y += vb * wv.y; B.z += vb * wv.z; B.w += vb * wv.w;
    }
    if (na < N_NODES) {
        float4 o;
        o.x = lrelu(A.x); o.y = lrelu(A.y); o.z = lrelu(A.z); o.w = lrelu(A.w);
        *(float4*)&h[(size_t)na * 64 + 4 * og] = o;
        hc[(size_t)na * 32 + 2 * og] = pack_h2(o.x, o.y);
        hc[(size_t)na * 32 + 2 * og + 1] = pack_h2(o.z, o.w);
        *(float4*)&agg[(size_t)na * 64 + 4 * og] = make_float4(0.f, 0.f, 0.f, 0.f);
    }
    if (nb < N_NODES) {
        float4 o;
        o.x = lrelu(B.x); o.y = lrelu(B.y); o.z = lrelu(B.z); o.w = lrelu(B.w);
        *(float4*)&h[(size_t)nb * 64 + 4 * og] = o;
        hc[(size_t)nb * 32 + 2 * og] = pack_h2(o.x, o.y);
        hc[(size_t)nb * 32 + 2 * og + 1] = pack_h2(o.z, o.w);
        *(float4*)&agg[(size_t)nb * 64 + 4 * og] = make_float4(0.f, 0.f, 0.f, 0.f);
    }
}

// ---------------- fused edge MLP (both layers): one thread per edge, broadcast weights ----------------
__global__ void __launch_bounds__(128) edge_mlp2_kernel(
    const float* __restrict__ ea,
    const float* __restrict__ w1a, const float* __restrict__ b1a,
    const float* __restrict__ w1b, const float* __restrict__ b1b,
    __half* __restrict__ tt1, __half* __restrict__ tt2) {
    __shared__ float eas[128 * 33];
    __shared__ float wA[32 * 64];
    __shared__ float wB[32 * 64];
    __shared__ float bA[64], bB[64];
    const int tid = threadIdx.x;
    const int tile = blockIdx.x;
    for (int idx = tid; idx < 128 * 32; idx += 128) {
        int e = idx >> 5, j = idx & 31;
        eas[e * 33 + j] = ea[tile * 4096 + idx];
    }
    for (int idx = tid; idx < 2048; idx += 128) { wA[idx] = w1a[idx]; wB[idx] = w1b[idx]; }
    if (tid < 64) { bA[tid] = b1a[tid]; bB[tid] = b1b[tid]; }
    __syncthreads();

    float ear[32];
#pragma unroll
    for (int j = 0; j < 32; ++j) ear[j] = eas[tid * 33 + j];

    __half* t1 = tt1 + tile * 8192 + tid;
    __half* t2 = tt2 + tile * 8192 + tid;
#pragma unroll 2
    for (int og = 0; og < 16; ++og) {
        float4 a1 = *(const float4*)&bA[4 * og];
        float4 a2 = *(const float4*)&bB[4 * og];
#pragma unroll
        for (int j = 0; j < 32; ++j) {
            float v = ear[j];
            float4 wa = *(const float4*)&wA[j * 64 + 4 * og];
            float4 wb = *(const float4*)&wB[j * 64 + 4 * og];
            a1.x += v * wa.x; a1.y += v * wa.y; a1.z += v * wa.z; a1.w += v * wa.w;
            a2.x += v * wb.x; a2.y += v * wb.y; a2.z += v * wb.z; a2.w += v * wb.w;
        }
        t1[(4 * og + 0) * 128] = __float2half(fmaxf(a1.x, 0.f));
        t1[(4 * og + 1) * 128] = __float2half(fmaxf(a1.y, 0.f));
        t1[(4 * og + 2) * 128] = __float2half(fmaxf(a1.z, 0.f));
        t1[(4 * og + 3) * 128] = __float2half(fmaxf(a1.w, 0.f));
        t2[(4 * og + 0) * 128] = __float2half(fmaxf(a2.x, 0.f));
        t2[(4 * og + 1) * 128] = __float2half(fmaxf(a2.y, 0.f));
        t2[(4 * og + 2) * 128] = __float2half(fmaxf(a2.z, 0.f));
        t2[(4 * og + 3) * 128] = __float2half(fmaxf(a2.w, 0.f));
    }
}

// ---------------- B prep (both layers): w2 (+b2) -> mma fragment order ----------------
__global__ void bprep2_kernel(const float* __restrict__ w2a, const float* __restrict__ b2a,
                              const float* __restrict__ w2b, const float* __restrict__ b2b,
                              uint4* __restrict__ bf) {
    int id = blockIdx.x * blockDim.x + threadIdx.x;  // < 2*65*512
    if (id >= 2 * NSLICE * FRAG_PER_SLICE) return;
    int layer = id >= NSLICE * FRAG_PER_SLICE;
    int rid = id - layer * NSLICE * FRAG_PER_SLICE;
    int s = rid >> 9;
    int f = rid & 511;
    int kt = f >> 7, np = (f >> 5) & 3, lane = f & 31;
    int tig = lane & 3, g = lane >> 2;
    const float* w2 = layer ? w2b : w2a;
    const float* b2 = layer ? b2b : b2a;
    int o0 = g + 16 * np, o1 = o0 + 8;
    int p0 = kt * 8 + tig, p1 = p0 + 4;
    auto rd = [&](int i, int o) -> float {
        return (s < 64) ? w2[(s << 12) + (i << 6) + o] : b2[(i << 6) + o];
    };
    auto pk = [&](int p, int o) -> uint32_t {
        return pack_h2(rd(2 * p, o), rd(2 * p + 1, o));
    };
    uint4 v;
    v.x = pk(p0, o0); v.y = pk(p1, o0); v.z = pk(p0, o1); v.w = pk(p1, o1);
    bf[id] = v;
}

// ---------------- fp16 mma.sync message GEMM + direct gather + scatter ----------------
// SMEM: B double-buffer 16KB + both subtiles' t tiles 32KB = 48KB (static limit)
__global__ void __launch_bounds__(256, 2) msg_mma_kernel(
    const __half* __restrict__ tt, const uint32_t* __restrict__ hc,
    const uint4* __restrict__ bf, float* __restrict__ agg) {
    __shared__ uint4 Bs[2][FRAG_PER_SLICE];
    __shared__ __half ts[2 * 8192];   // [subtile-in-CTA][k][e]
    const int tid = threadIdx.x;
    const int w = tid >> 5, lane = tid & 31;
    const int g = lane >> 2, tig = lane & 3;
    const int subtile = 2 * blockIdx.x + (w >> 2);
    const int wl = w & 3;

    {
        // B slice 0 (2 chunks/thread) + both t tiles (8 chunks/thread), one group
        cp16(&Bs[0][tid], bf + tid);
        cp16(&Bs[0][tid + 256], bf + tid + 256);
        const __half* tsrc = tt + (size_t)(2 * blockIdx.x) * 8192;
#pragma unroll
        for (int q = 0; q < 8; ++q) {
            int c = tid + q * 256;               // 2048 chunks of 16B
            cp16(&ts[c * 8], tsrc + c * 8);
        }
        cp_commit();
    }

    // direct gather: hh[m][r][j] = hc[src[e(m,r)]][tig + 4j]
    const int ebase = subtile * 128 + wl * 32 + g;
    uint32_t hh[2][2][8];
#pragma unroll
    for (int m = 0; m < 2; ++m)
#pragma unroll
        for (int r = 0; r < 2; ++r) {
            const int e = ebase + m * 16 + r * 8;
            const uint32_t* hp = hc + (size_t)g_src[e] * 32 + tig;
#pragma unroll
            for (int j = 0; j < 8; ++j) hh[m][r][j] = hp[4 * j];
        }

    float C[2][8][4];
#pragma unroll
    for (int m = 0; m < 2; ++m)
#pragma unroll
        for (int nt = 0; nt < 8; ++nt)
#pragma unroll
            for (int q = 0; q < 4; ++q) C[m][nt][q] = 0.f;

    const __half* tbase = ts + (w >> 2) * 8192 + wl * 32 + g;

    for (int k = 0; k < NSLICE; ++k) {
        const int b = k & 1;
        asm volatile("cp.async.wait_group 0;");
        __syncthreads();
        if (k < NSLICE - 1) {
            const uint4* s = bf + (size_t)(k + 1) * FRAG_PER_SLICE;
            uint4* d = Bs[b ^ 1];
            cp16(&d[tid], s + tid);
            cp16(&d[tid + 256], s + tid + 256);
            cp_commit();
        }

        __half2 t2[4];
        if (k < 64) {
            const __half* tp = tbase + k * 128;   // SMEM now
            t2[0] = __half2half2(tp[0]);
            t2[1] = __half2half2(tp[8]);
            t2[2] = __half2half2(tp[16]);
            t2[3] = __half2half2(tp[24]);
        } else {
            t2[0] = t2[1] = t2[2] = t2[3] = __float2half2_rn(1.f);
        }

        const uint4* B = Bs[b];
#pragma unroll
        for (int kt = 0; kt < 4; ++kt) {
            __half2 a[2][4];
#pragma unroll
            for (int m = 0; m < 2; ++m) {
                a[m][0] = __hmul2(*(const __half2*)&hh[m][0][2 * kt + 0], t2[2 * m + 0]);
                a[m][1] = __hmul2(*(const __half2*)&hh[m][1][2 * kt + 0], t2[2 * m + 1]);
                a[m][2] = __hmul2(*(const __half2*)&hh[m][0][2 * kt + 1], t2[2 * m + 0]);
                a[m][3] = __hmul2(*(const __half2*)&hh[m][1][2 * kt + 1], t2[2 * m + 1]);
            }
#pragma unroll
            for (int np = 0; np < 4; ++np) {
                uint4 bv = B[(kt * 4 + np) * 32 + lane];
                mma16(C[0][2 * np + 0], reinterpret_cast<const uint32_t*>(a[0]), bv.x, bv.y);
                mma16(C[1][2 * np + 0], reinterpret_cast<const uint32_t*>(a[1]), bv.x, bv.y);
                mma16(C[0][2 * np + 1], reinterpret_cast<const uint32_t*>(a[0]), bv.z, bv.w);
                mma16(C[1][2 * np + 1], reinterpret_cast<const uint32_t*>(a[1]), bv.z, bv.w);
            }
        }
    }

#pragma unroll
    for (int m = 0; m < 2; ++m) {
        int d0 = g_dst[ebase + m * 16];
        int d1 = g_dst[ebase + m * 16 + 8];
        float* p0 = agg + (size_t)d0 * 64 + 2 * tig;
        float* p1 = agg + (size_t)d1 * 64 + 2 * tig;
#pragma unroll
        for (int nt = 0; nt < 8; ++nt) {
            red2(p0 + nt * 8, C[m][nt][0], C[m][nt][1]);
            red2(p1 + nt * 8, C[m][nt][2], C[m][nt][3]);
        }
    }
}

// ---------------- node update: thread-per-node; emits fp16 copy; zeroes agg ----------------
__global__ void __launch_bounds__(128) node_update_kernel(
    const float* __restrict__ hin, float* __restrict__ agg,
    const float* __restrict__ root, const float* __restrict__ bias,
    float* __restrict__ hout, uint32_t* __restrict__ hc) {
    __shared__ float rs[64 * 64];
    __shared__ float bs[64];
    const int tid = threadIdx.x;
    for (int idx = tid; idx < 4096; idx += 128) rs[idx] = root[idx];
    if (tid < 64) bs[tid] = bias[tid];
    __syncthreads();

    const int n = blockIdx.x * 128 + tid;
    if (n >= N_NODES) return;

    float* ap = agg + (size_t)n * 64;
    float4 acc[16];
#pragma unroll
    for (int og = 0; og < 16; ++og) {
        float4 a = *(const float4*)&ap[4 * og];
        const float4 bv = *(const float4*)&bs[4 * og];
        a.x += bv.x; a.y += bv.y; a.z += bv.z; a.w += bv.w;
        acc[og] = a;
    }
#pragma unroll
    for (int og = 0; og < 16; ++og)
        *(float4*)&ap[4 * og] = make_float4(0.f, 0.f, 0.f, 0.f);

    const float* hp = hin + (size_t)n * 64;
#pragma unroll
    for (int ig = 0; ig < 4; ++ig) {
        float4 hv[4];
#pragma unroll
        for (int q = 0; q < 4; ++q) hv[q] = *(const float4*)&hp[ig * 16 + 4 * q];
        const float* hr = (const float*)hv;
#pragma unroll
        for (int j = 0; j < 16; ++j) {
            float v = hr[j];
            const float* rr = rs + (ig * 16 + j) * 64;
#pragma unroll
            for (int og = 0; og < 16; ++og) {
                float4 rv = *(const float4*)&rr[4 * og];
                acc[og].x += v * rv.x; acc[og].y += v * rv.y;
                acc[og].z += v * rv.z; acc[og].w += v * rv.w;
            }
        }
    }

    float* op = hout + (size_t)n * 64;
    uint32_t* hcp = hc + (size_t)n * 32;
#pragma unroll
    for (int og = 0; og < 16; ++og) {
        float4 o;
        o.x = lrelu(acc[og].x); o.y = lrelu(acc[og].y);
        o.z = lrelu(acc[og].z); o.w = lrelu(acc[og].w);
        *(float4*)&op[4 * og] = o;
        hcp[2 * og] = pack_h2(o.x, o.y);
        hcp[2 * og + 1] = pack_h2(o.z, o.w);
    }
}

// ---------------- global add pool (batch-sorted running-sum flush) ----------------
__global__ void pool_kernel(const float* __restrict__ h) {
    const int tid = threadIdx.x;
    const int o = tid & 63, q = tid >> 6;
    const int nbase = blockIdx.x * 256 + q * 64;
    float run = 0.f;
    int curb = -1;
    for (int j = 0; j < 64; ++j) {
        int n = nbase + j;
        if (n >= N_NODES) break;
        int bn = g_bat[n];
        if (bn != curb) {
            if (curb >= 0) atomicAdd(&g_hg[curb * 64 + o], run);
            run = 0.f;
            curb = bn;
        }
        run += h[(size_t)n * 64 + o];
    }
    if (curb >= 0) atomicAdd(&g_hg[curb * 64 + o], run);
}

// ---------------- readout head ----------------
__global__ void head_kernel(const float* __restrict__ fc1w, const float* __restrict__ fc1b,
                            const float* __restrict__ fc2w, const float* __restrict__ fc2b,
                            float* __restrict__ out) {
    __shared__ float hs[N_GRAPHS * HID];
    int g = threadIdx.x;
    for (int i = g; i < N_GRAPHS * HID; i += 64) hs[i] = g_hg[i];
    __syncthreads();
    float acc = fc2b[0];
#pragma unroll 4
    for (int j = 0; j < 32; ++j) {
        float s = fc1b[j];
#pragma unroll 8
        for (int i = 0; i < 64; ++i) s += hs[g * 64 + i] * fc1w[i * 32 + j];
        acc += lrelu(s) * fc2w[j];
    }
    out[g] = acc;
}

// ---------------- launch ----------------
extern "C" void kernel_launch(void* const* d_in, const int* in_sizes, int n_in,
                              void* d_out, int out_size) {
    const float* x     = (const float*)d_in[0];
    const void*  ei    = d_in[1];
    const float* ea    = (const float*)d_in[2];
    const void*  bat   = d_in[3];
    const float* nfc_w = (const float*)d_in[4];
    const float* nfc_b = (const float*)d_in[5];
    const float* e1w1  = (const float*)d_in[6];
    const float* e1b1  = (const float*)d_in[7];
    const float* e1w2  = (const float*)d_in[8];
    const float* e1b2  = (const float*)d_in[9];
    const float* root1 = (const float*)d_in[10];
    const float* bias1 = (const float*)d_in[11];
    const float* e2w1  = (const float*)d_in[12];
    const float* e2b1  = (const float*)d_in[13];
    const float* e2w2  = (const float*)d_in[14];
    const float* e2b2  = (const float*)d_in[15];
    const float* root2 = (const float*)d_in[16];
    const float* bias2 = (const float*)d_in[17];
    const float* fc1w  = (const float*)d_in[18];
    const float* fc1b  = (const float*)d_in[19];
    const float* fc2w  = (const float*)d_in[20];
    const float* fc2b  = (const float*)d_in[21];
    float* out = (float*)d_out;

    float *h0, *h1, *agg, *hg;
    __half *tt1, *tt2;
    uint32_t* hc;
    uint4* bfp;
    cudaGetSymbolAddress((void**)&h0, g_h0);
    cudaGetSymbolAddress((void**)&h1, g_h1);
    cudaGetSymbolAddress((void**)&agg, g_agg);
    cudaGetSymbolAddress((void**)&tt1, g_tt1);
    cudaGetSymbolAddress((void**)&tt2, g_tt2);
    cudaGetSymbolAddress((void**)&hg, g_hg);
    cudaGetSymbolAddress((void**)&hc, g_hc);
    cudaGetSymbolAddress((void**)&bfp, g_bfrag);

    // fork: edge MLP + weight prep + index convert on aux stream; node encoder on main
    cudaEventRecord(g_aux.fork, 0);
    cudaStreamWaitEvent(g_aux.s1, g_aux.fork, 0);
    edge_mlp2_kernel<<<NTILES, 128, 0, g_aux.s1>>>(ea, e1w1, e1b1, e2w1, e2b1, tt1, tt2);
    bprep2_kernel<<<(2 * NSLICE * FRAG_PER_SLICE + 255) / 256, 256, 0, g_aux.s1>>>(
        e1w2, e1b2, e2w2, e2b2, bfp);
    convert_idx_kernel<<<256, 256, 0, g_aux.s1>>>(ei, bat);
    cudaEventRecord(g_aux.join, g_aux.s1);

    node_enc_kernel<<<(N_NODES + 31) / 32, 256>>>(x, nfc_w, nfc_b, h0, hc, agg);

    cudaStreamWaitEvent(0, g_aux.join, 0);

    // layer 1
    msg_mma_kernel<<<NTILES / 2, 256>>>(tt1, hc, bfp, agg);
    node_update_kernel<<<(N_NODES + 127) / 128, 128>>>(h0, agg, root1, bias1, h1, hc);

    // layer 2
    msg_mma_kernel<<<NTILES / 2, 256>>>(tt2, hc, bfp + (size_t)NSLICE * FRAG_PER_SLICE, agg);
    node_update_kernel<<<(N_NODES + 127) / 128, 128>>>(h1, agg, root2, bias2, h0, hc);

    // pool + head
    pool_kernel<<<(N_NODES + 255) / 256, 256>>>(h0);
    head_kernel<<<1, 64>>>(fc1w, fc1b, fc2w, fc2b, out);
}